// round 2
// baseline (speedup 1.0000x reference)
#include <cuda_runtime.h>
#include <math.h>

#define Bsz 256
#define Tt  500
#define Ii  128
#define Hh  512
#define CLIPV 5.0f
#define KC  32
#define NT1 (Hh/KC)    // 16 h-phase k-tiles
#define NT2 (Ii/KC)    // 4  x-phase k-tiles
#define NTT (NT1+NT2)  // 20

typedef unsigned long long ull;

// Double-buffered hidden state (scratch via __device__ globals — no allocation).
__device__ float g_h[2][Bsz * Hh];

__device__ __forceinline__ ull fma2(ull a, ull b, ull c) {
    ull d;
    asm("fma.rn.f32x2 %0, %1, %2, %3;" : "=l"(d) : "l"(a), "l"(b), "l"(c));
    return d;
}
__device__ __forceinline__ ull dup2(float f) {
    unsigned u = __float_as_uint(f);
    return ((ull)u << 32) | (ull)u;
}
__device__ __forceinline__ float lo2(ull v) { return __uint_as_float((unsigned)v); }
__device__ __forceinline__ float hi2(ull v) { return __uint_as_float((unsigned)(v >> 32)); }
__device__ __forceinline__ float sigf(float x) { return 1.f / (1.f + __expf(-x)); }

__global__ void init_h(const float* __restrict__ h0) {
    int i = blockIdx.x * blockDim.x + threadIdx.x;
    if (i < Bsz * Hh) g_h[0][i] = h0[i];
}
// 500 steps -> final h in g_h[0]
__global__ void copy_hlast(float* __restrict__ dst) {
    int i = blockIdx.x * blockDim.x + threadIdx.x;
    if (i < Bsz * Hh) dst[i] = g_h[0][i];
}

// One GRU timestep. Tile: 32 batch x 32 hidden x 3 gates, K = 512 (h) + 128 (x).
// 128 threads: tx = m-pair index (16), ty = batch quad index (8).
// Per-thread micro-tile: 4 batches x 2 m x 3 gates, accumulated in f32x2 (FFMA2).
// Smem: h stored pre-duplicated ({h,h} ull) so packed FMA needs no per-kk MOVs;
// w stored plain fp32, read as float2 (m-pairs). Single-sync reg-staged pipeline.
__global__ void __launch_bounds__(128) gru_step(
    const float* __restrict__ x,      // (B, T, I)
    const float* __restrict__ w_ih,   // (3H, I)
    const float* __restrict__ w_hh,   // (3H, H)
    const float* __restrict__ b_ih,   // (3H)
    const float* __restrict__ b_hh,   // (3H)
    float* __restrict__ out,          // (B, T, H) then (B, H) tail
    int t)
{
    const float* __restrict__ h_in  = g_h[t & 1];
    float* __restrict__       h_out = g_h[(t + 1) & 1];

    __shared__ alignas(16) ull   Hs[2][KC][32];      // [buf][k][b] dup'd {h,h}
    __shared__ alignas(16) float Ws[2][3][KC][32];   // [buf][g][k][m]

    const int tid = threadIdx.x;
    const int tx  = tid & 15;          // m-pair: m = m0 + 2*tx + {0,1}
    const int ty  = tid >> 4;          // batch quad: b = b0 + 4*ty + {0..3}
    const int m0  = blockIdx.x * 32;
    const int b0  = blockIdx.y * 32;
    const int mm  = tid & 31;          // loader row within tile
    const int kq  = tid >> 5;          // loader k-slot group (0..3)

    ull acc[4][3];                     // r,z shared x+h; [.,2] = h-side n
    ull accX[4];                       // x-side n
    #pragma unroll
    for (int b = 0; b < 4; b++) {
        accX[b] = 0ull;
        #pragma unroll
        for (int g = 0; g < 3; g++) acc[b][g] = 0ull;
    }

    // register staging for the global->smem pipeline
    float4 sh0, sh1;
    float4 sw[3][2];

    auto ldg_tile = [&](int tt) {
        if (tt < NT1) {
            const int k0 = tt * KC;
            const float* hp = &h_in[(b0 + mm) * Hh + k0 + 4 * kq];
            sh0 = *reinterpret_cast<const float4*>(hp);
            sh1 = *reinterpret_cast<const float4*>(hp + 16);
            #pragma unroll
            for (int g = 0; g < 3; g++) {
                const float* wp = &w_hh[(g * Hh + m0 + mm) * Hh + k0 + 4 * kq];
                sw[g][0] = *reinterpret_cast<const float4*>(wp);
                sw[g][1] = *reinterpret_cast<const float4*>(wp + 16);
            }
        } else {
            const int k0 = (tt - NT1) * KC;
            const float* xp = &x[((size_t)(b0 + mm) * Tt + t) * Ii + k0 + 4 * kq];
            sh0 = *reinterpret_cast<const float4*>(xp);
            sh1 = *reinterpret_cast<const float4*>(xp + 16);
            #pragma unroll
            for (int g = 0; g < 3; g++) {
                const float* wp = &w_ih[(g * Hh + m0 + mm) * Ii + k0 + 4 * kq];
                sw[g][0] = *reinterpret_cast<const float4*>(wp);
                sw[g][1] = *reinterpret_cast<const float4*>(wp + 16);
            }
        }
    };

    auto sts_tile = [&](int buf) {
        const int ka = 4 * kq;          // slots kq and kq+4 -> k offsets 4kq, 4kq+16
        Hs[buf][ka + 0][mm]  = dup2(sh0.x);
        Hs[buf][ka + 1][mm]  = dup2(sh0.y);
        Hs[buf][ka + 2][mm]  = dup2(sh0.z);
        Hs[buf][ka + 3][mm]  = dup2(sh0.w);
        Hs[buf][ka + 16][mm] = dup2(sh1.x);
        Hs[buf][ka + 17][mm] = dup2(sh1.y);
        Hs[buf][ka + 18][mm] = dup2(sh1.z);
        Hs[buf][ka + 19][mm] = dup2(sh1.w);
        #pragma unroll
        for (int g = 0; g < 3; g++) {
            Ws[buf][g][ka + 0][mm]  = sw[g][0].x;
            Ws[buf][g][ka + 1][mm]  = sw[g][0].y;
            Ws[buf][g][ka + 2][mm]  = sw[g][0].z;
            Ws[buf][g][ka + 3][mm]  = sw[g][0].w;
            Ws[buf][g][ka + 16][mm] = sw[g][1].x;
            Ws[buf][g][ka + 17][mm] = sw[g][1].y;
            Ws[buf][g][ka + 18][mm] = sw[g][1].z;
            Ws[buf][g][ka + 19][mm] = sw[g][1].w;
        }
    };

    auto compute_p1 = [&](int buf) {
        #pragma unroll
        for (int kk = 0; kk < KC; kk++) {
            ull w0 = *reinterpret_cast<const ull*>(&Ws[buf][0][kk][2 * tx]);
            ull w1 = *reinterpret_cast<const ull*>(&Ws[buf][1][kk][2 * tx]);
            ull w2 = *reinterpret_cast<const ull*>(&Ws[buf][2][kk][2 * tx]);
            ulonglong2 ha = *reinterpret_cast<const ulonglong2*>(&Hs[buf][kk][4 * ty]);
            ulonglong2 hb = *reinterpret_cast<const ulonglong2*>(&Hs[buf][kk][4 * ty + 2]);
            ull hv[4] = {ha.x, ha.y, hb.x, hb.y};
            #pragma unroll
            for (int b = 0; b < 4; b++) {
                acc[b][0] = fma2(hv[b], w0, acc[b][0]);
                acc[b][1] = fma2(hv[b], w1, acc[b][1]);
                acc[b][2] = fma2(hv[b], w2, acc[b][2]);
            }
        }
    };
    auto compute_p2 = [&](int buf) {
        #pragma unroll
        for (int kk = 0; kk < KC; kk++) {
            ull w0 = *reinterpret_cast<const ull*>(&Ws[buf][0][kk][2 * tx]);
            ull w1 = *reinterpret_cast<const ull*>(&Ws[buf][1][kk][2 * tx]);
            ull w2 = *reinterpret_cast<const ull*>(&Ws[buf][2][kk][2 * tx]);
            ulonglong2 ha = *reinterpret_cast<const ulonglong2*>(&Hs[buf][kk][4 * ty]);
            ulonglong2 hb = *reinterpret_cast<const ulonglong2*>(&Hs[buf][kk][4 * ty + 2]);
            ull hv[4] = {ha.x, ha.y, hb.x, hb.y};
            #pragma unroll
            for (int b = 0; b < 4; b++) {
                acc[b][0] = fma2(hv[b], w0, acc[b][0]);
                acc[b][1] = fma2(hv[b], w1, acc[b][1]);
                accX[b]   = fma2(hv[b], w2, accX[b]);
            }
        }
    };

    // pipeline prologue
    ldg_tile(0);
    sts_tile(0);
    ldg_tile(1);
    __syncthreads();

    for (int tt = 0; tt < NTT; tt++) {
        const int buf = tt & 1;
        if (tt + 1 < NTT) sts_tile((tt + 1) & 1);  // buf last read at tile tt-1
        if (tt + 2 < NTT) ldg_tile(tt + 2);
        if (tt < NT1) compute_p1(buf); else compute_p2(buf);
        __syncthreads();
    }

    // ---------------- Epilogue ----------------
    const int m = m0 + 2 * tx;
    float2 bir = *reinterpret_cast<const float2*>(&b_ih[m]);
    float2 biz = *reinterpret_cast<const float2*>(&b_ih[Hh + m]);
    float2 bin = *reinterpret_cast<const float2*>(&b_ih[2 * Hh + m]);
    float2 bhr = *reinterpret_cast<const float2*>(&b_hh[m]);
    float2 bhz = *reinterpret_cast<const float2*>(&b_hh[Hh + m]);
    float2 bhn = *reinterpret_cast<const float2*>(&b_hh[2 * Hh + m]);

    #pragma unroll
    for (int b = 0; b < 4; b++) {
        const int bg = b0 + 4 * ty + b;
        float2 hp = *reinterpret_cast<const float2*>(&h_in[bg * Hh + m]);

        float rl = sigf(lo2(acc[b][0]) + bir.x + bhr.x);
        float rh = sigf(hi2(acc[b][0]) + bir.y + bhr.y);
        float zl = sigf(lo2(acc[b][1]) + biz.x + bhz.x);
        float zh = sigf(hi2(acc[b][1]) + biz.y + bhz.y);
        float nl = tanhf(lo2(accX[b]) + bin.x + rl * (lo2(acc[b][2]) + bhn.x));
        float nh = tanhf(hi2(accX[b]) + bin.y + rh * (hi2(acc[b][2]) + bhn.y));

        float hl = (1.f - zl) * nl + zl * hp.x;
        float hh = (1.f - zh) * nh + zh * hp.y;
        hl = fminf(fmaxf(hl, -CLIPV), CLIPV);
        hh = fminf(fmaxf(hh, -CLIPV), CLIPV);

        float2 res = make_float2(hl, hh);
        *reinterpret_cast<float2*>(&h_out[bg * Hh + m]) = res;
        *reinterpret_cast<float2*>(&out[((size_t)bg * Tt + t) * Hh + m]) = res;
    }
}

extern "C" void kernel_launch(void* const* d_in, const int* in_sizes, int n_in,
                              void* d_out, int out_size)
{
    (void)in_sizes; (void)n_in; (void)out_size;
    const float* x    = (const float*)d_in[0];
    const float* h0   = (const float*)d_in[1];
    const float* w_ih = (const float*)d_in[2];
    const float* w_hh = (const float*)d_in[3];
    const float* b_ih = (const float*)d_in[4];
    const float* b_hh = (const float*)d_in[5];
    float* out = (float*)d_out;

    init_h<<<(Bsz * Hh + 255) / 256, 256>>>(h0);

    dim3 grid(Hh / 32, Bsz / 32);   // 16 x 8 = 128 blocks
    for (int t = 0; t < Tt; t++) {
        gru_step<<<grid, 128>>>(x, w_ih, w_hh, b_ih, b_hh, out, t);
    }

    copy_hlast<<<(Bsz * Hh + 255) / 256, 256>>>(out + (size_t)Bsz * Tt * Hh);
}

// round 3
// speedup vs baseline: 1.1730x; 1.1730x over previous
#include <cuda_runtime.h>
#include <math.h>

#define Bsz 256
#define Tt  500
#define Ii  128
#define Hh  512
#define CLIPV 5.0f
#define KC  32
#define NTILES 20          // 16 h-phase + 4 x-phase k-tiles
#define NSPLIT 4
#define TPS (NTILES / NSPLIT)   // 5 tiles per split

// per-split smem: Hs ull[2][KC][32] = 16KB, Ws float[2][3][KC][32] = 24KB
#define SPLIT_SMEM 40960
#define SMEM_BYTES (NSPLIT * SPLIT_SMEM)   // 160 KB

typedef unsigned long long ull;

__device__ float g_h[2][Bsz * Hh];

__device__ __forceinline__ ull fma2(ull a, ull b, ull c) {
    ull d;
    asm("fma.rn.f32x2 %0, %1, %2, %3;" : "=l"(d) : "l"(a), "l"(b), "l"(c));
    return d;
}
__device__ __forceinline__ ull add2(ull a, ull b) {
    ull d;
    asm("add.rn.f32x2 %0, %1, %2;" : "=l"(d) : "l"(a), "l"(b));
    return d;
}
__device__ __forceinline__ ull dup2(float f) {
    unsigned u = __float_as_uint(f);
    return ((ull)u << 32) | (ull)u;
}
__device__ __forceinline__ float lo2(ull v) { return __uint_as_float((unsigned)v); }
__device__ __forceinline__ float hi2(ull v) { return __uint_as_float((unsigned)(v >> 32)); }
__device__ __forceinline__ float sigf(float x) { return 1.f / (1.f + __expf(-x)); }

__global__ void init_h(const float* __restrict__ h0) {
    int i = blockIdx.x * blockDim.x + threadIdx.x;
    if (i < Bsz * Hh) g_h[0][i] = h0[i];
}
__global__ void copy_hlast(float* __restrict__ dst) {
    int i = blockIdx.x * blockDim.x + threadIdx.x;
    if (i < Bsz * Hh) dst[i] = g_h[0][i];
}

// One GRU timestep. Output tile 32 batch x 32 hidden x 3 gates, K = 640.
// 512 threads = 4 K-splits x 128 threads. Each split: 5 k-tiles of KC=32,
// double-buffered smem, named-barrier synced (4 warps each, ids 1..4).
// Cross-split reduction in smem, epilogue on split 0.
__global__ void __launch_bounds__(512, 1) gru_step(
    const float* __restrict__ x,      // (B, T, I)
    const float* __restrict__ w_ih,   // (3H, I)
    const float* __restrict__ w_hh,   // (3H, H)
    const float* __restrict__ b_ih,   // (3H)
    const float* __restrict__ b_hh,   // (3H)
    float* __restrict__ out,          // (B, T, H) then (B, H) tail
    int t)
{
    extern __shared__ char smem_raw[];

    const float* __restrict__ h_in  = g_h[t & 1];
    float* __restrict__       h_out = g_h[(t + 1) & 1];

    const int tid   = threadIdx.x;
    const int split = tid >> 7;        // 0..3
    const int stid  = tid & 127;
    const int barid = split + 1;       // named barrier ids 1..4

    typedef ull   HsT[KC][32];
    typedef float WsT[3][KC][32];
    HsT* Hs = (HsT*)(smem_raw + split * SPLIT_SMEM);                 // [2][KC][32] ull
    WsT* Ws = (WsT*)(smem_raw + split * SPLIT_SMEM + 16384);         // [2][3][KC][32] f32

    const int tx = stid & 15;          // m-pair: m = m0 + 2*tx + {0,1}
    const int ty = stid >> 4;          // batch quad: b = b0 + 4*ty + {0..3}
    const int m0 = blockIdx.x * 32;
    const int b0 = blockIdx.y * 32;
    const int mm = stid & 31;          // loader row within tile
    const int kq = stid >> 5;          // loader k-slot group (0..3)

    ull acc[4][3];                     // [b][g]: r, z (x+h combined), h-side n
    ull accX[4];                       // x-side n
    #pragma unroll
    for (int b = 0; b < 4; b++) {
        accX[b] = 0ull;
        #pragma unroll
        for (int g = 0; g < 3; g++) acc[b][g] = 0ull;
    }

    float4 sh0, sh1;
    float4 sw[3][2];

    auto ldg_tile = [&](int g) {       // g = global tile index 0..19
        const float* hp;
        const float* wb;
        int wstride, k0;
        if (g < 16) {
            k0 = g * KC; wb = w_hh; wstride = Hh;
            hp = &h_in[(b0 + mm) * Hh + k0 + 4 * kq];
        } else {
            k0 = (g - 16) * KC; wb = w_ih; wstride = Ii;
            hp = &x[((size_t)(b0 + mm) * Tt + t) * Ii + k0 + 4 * kq];
        }
        sh0 = *reinterpret_cast<const float4*>(hp);
        sh1 = *reinterpret_cast<const float4*>(hp + 16);
        #pragma unroll
        for (int gg = 0; gg < 3; gg++) {
            const float* wp = &wb[(size_t)(gg * Hh + m0 + mm) * wstride + k0 + 4 * kq];
            sw[gg][0] = *reinterpret_cast<const float4*>(wp);
            sw[gg][1] = *reinterpret_cast<const float4*>(wp + 16);
        }
    };

    auto sts_tile = [&](int buf) {
        const int ka = 4 * kq;
        Hs[buf][ka + 0][mm]  = dup2(sh0.x);
        Hs[buf][ka + 1][mm]  = dup2(sh0.y);
        Hs[buf][ka + 2][mm]  = dup2(sh0.z);
        Hs[buf][ka + 3][mm]  = dup2(sh0.w);
        Hs[buf][ka + 16][mm] = dup2(sh1.x);
        Hs[buf][ka + 17][mm] = dup2(sh1.y);
        Hs[buf][ka + 18][mm] = dup2(sh1.z);
        Hs[buf][ka + 19][mm] = dup2(sh1.w);
        #pragma unroll
        for (int gg = 0; gg < 3; gg++) {
            Ws[buf][gg][ka + 0][mm]  = sw[gg][0].x;
            Ws[buf][gg][ka + 1][mm]  = sw[gg][0].y;
            Ws[buf][gg][ka + 2][mm]  = sw[gg][0].z;
            Ws[buf][gg][ka + 3][mm]  = sw[gg][0].w;
            Ws[buf][gg][ka + 16][mm] = sw[gg][1].x;
            Ws[buf][gg][ka + 17][mm] = sw[gg][1].y;
            Ws[buf][gg][ka + 18][mm] = sw[gg][1].z;
            Ws[buf][gg][ka + 19][mm] = sw[gg][1].w;
        }
    };

    auto compute = [&](int buf, bool hphase) {
        #pragma unroll
        for (int kk = 0; kk < KC; kk++) {
            ull w0 = *reinterpret_cast<const ull*>(&Ws[buf][0][kk][2 * tx]);
            ull w1 = *reinterpret_cast<const ull*>(&Ws[buf][1][kk][2 * tx]);
            ull w2 = *reinterpret_cast<const ull*>(&Ws[buf][2][kk][2 * tx]);
            ulonglong2 ha = *reinterpret_cast<const ulonglong2*>(&Hs[buf][kk][4 * ty]);
            ulonglong2 hb = *reinterpret_cast<const ulonglong2*>(&Hs[buf][kk][4 * ty + 2]);
            ull hv[4] = {ha.x, ha.y, hb.x, hb.y};
            #pragma unroll
            for (int b = 0; b < 4; b++) {
                acc[b][0] = fma2(hv[b], w0, acc[b][0]);
                acc[b][1] = fma2(hv[b], w1, acc[b][1]);
                if (hphase) acc[b][2] = fma2(hv[b], w2, acc[b][2]);
                else        accX[b]   = fma2(hv[b], w2, accX[b]);
            }
        }
    };

    const int g0 = split * TPS;

    // per-split pipeline (named barrier syncs only this split's 4 warps)
    ldg_tile(g0);
    sts_tile(0);
    ldg_tile(g0 + 1);
    asm volatile("bar.sync %0, 128;" :: "r"(barid) : "memory");

    #pragma unroll
    for (int i = 0; i < TPS; i++) {
        const int buf = i & 1;
        if (i + 1 < TPS) sts_tile((i + 1) & 1);
        if (i + 2 < TPS) ldg_tile(g0 + i + 2);
        compute(buf, (g0 + i) < 16);
        asm volatile("bar.sync %0, 128;" :: "r"(barid) : "memory");
    }

    // -------- cross-split reduction (reuses tile smem after full-block sync) --------
    __syncthreads();
    ulonglong2* red = (ulonglong2*)smem_raw;   // red[p][tid], p = 0..7 : 64 KB
    #pragma unroll
    for (int b = 0; b < 4; b++) {
        red[b * 512 + tid]       = make_ulonglong2(acc[b][0], acc[b][1]);
        red[(4 + b) * 512 + tid] = make_ulonglong2(acc[b][2], accX[b]);
    }
    __syncthreads();

    if (split != 0) return;

    #pragma unroll
    for (int s = 1; s < NSPLIT; s++) {
        #pragma unroll
        for (int b = 0; b < 4; b++) {
            ulonglong2 v0 = red[b * 512 + stid + 128 * s];
            ulonglong2 v1 = red[(4 + b) * 512 + stid + 128 * s];
            acc[b][0] = add2(acc[b][0], v0.x);
            acc[b][1] = add2(acc[b][1], v0.y);
            acc[b][2] = add2(acc[b][2], v1.x);
            accX[b]   = add2(accX[b],   v1.y);
        }
    }

    // ---------------- Epilogue (split 0 only) ----------------
    const int m = m0 + 2 * tx;
    float2 bir = *reinterpret_cast<const float2*>(&b_ih[m]);
    float2 biz = *reinterpret_cast<const float2*>(&b_ih[Hh + m]);
    float2 bin = *reinterpret_cast<const float2*>(&b_ih[2 * Hh + m]);
    float2 bhr = *reinterpret_cast<const float2*>(&b_hh[m]);
    float2 bhz = *reinterpret_cast<const float2*>(&b_hh[Hh + m]);
    float2 bhn = *reinterpret_cast<const float2*>(&b_hh[2 * Hh + m]);

    #pragma unroll
    for (int b = 0; b < 4; b++) {
        const int bg = b0 + 4 * ty + b;
        float2 hp = *reinterpret_cast<const float2*>(&h_in[bg * Hh + m]);

        float rl = sigf(lo2(acc[b][0]) + bir.x + bhr.x);
        float rh = sigf(hi2(acc[b][0]) + bir.y + bhr.y);
        float zl = sigf(lo2(acc[b][1]) + biz.x + bhz.x);
        float zh = sigf(hi2(acc[b][1]) + biz.y + bhz.y);
        float nl = tanhf(lo2(accX[b]) + bin.x + rl * (lo2(acc[b][2]) + bhn.x));
        float nh = tanhf(hi2(accX[b]) + bin.y + rh * (hi2(acc[b][2]) + bhn.y));

        float hl = (1.f - zl) * nl + zl * hp.x;
        float hh = (1.f - zh) * nh + zh * hp.y;
        hl = fminf(fmaxf(hl, -CLIPV), CLIPV);
        hh = fminf(fmaxf(hh, -CLIPV), CLIPV);

        float2 res = make_float2(hl, hh);
        *reinterpret_cast<float2*>(&h_out[bg * Hh + m]) = res;
        *reinterpret_cast<float2*>(&out[((size_t)bg * Tt + t) * Hh + m]) = res;
    }
}

extern "C" void kernel_launch(void* const* d_in, const int* in_sizes, int n_in,
                              void* d_out, int out_size)
{
    (void)in_sizes; (void)n_in; (void)out_size;
    const float* x    = (const float*)d_in[0];
    const float* h0   = (const float*)d_in[1];
    const float* w_ih = (const float*)d_in[2];
    const float* w_hh = (const float*)d_in[3];
    const float* b_ih = (const float*)d_in[4];
    const float* b_hh = (const float*)d_in[5];
    float* out = (float*)d_out;

    static int smem_set = 0;
    if (!smem_set) {
        cudaFuncSetAttribute(gru_step, cudaFuncAttributeMaxDynamicSharedMemorySize,
                             SMEM_BYTES);
        smem_set = 1;
    }

    init_h<<<(Bsz * Hh + 255) / 256, 256>>>(h0);

    dim3 grid(Hh / 32, Bsz / 32);   // 16 x 8 = 128 blocks
    for (int t = 0; t < Tt; t++) {
        gru_step<<<grid, 512, SMEM_BYTES>>>(x, w_ih, w_hh, b_ih, b_hh, out, t);
    }

    copy_hlast<<<(Bsz * Hh + 255) / 256, 256>>>(out + (size_t)Bsz * Tt * Hh);
}

// round 4
// speedup vs baseline: 1.4813x; 1.2629x over previous
#include <cuda_runtime.h>
#include <math.h>

#define Bsz 256
#define Tt  500
#define Ii  128
#define Hh  512
#define CLIPV 5.0f

#define NBLK 128        // 32 m-tiles x 4 batch-tiles, 1 block/SM, all co-resident
#define NTHR 256
#define MT   16         // m columns per block (x3 gates)
#define BT   64         // batches per block
#define KTOT 640        // 512 (h) + 128 (x)
#define KCH  64
#define NCH  10         // 8 h-chunks + 2 x-chunks

// smem layout (dynamic):
//  W01: ulonglong2[640][8]  (r,z m-pair packed)   81920 B
//  W2 : ull       [640][8]  (n m-pair packed)     40960 B
//  Hs : float  [2][64][66]  (staged h/x, swizzle) 33792 B
#define SM_W01 0
#define SM_W2  81920
#define SM_HS  (81920 + 40960)
#define SMEM_BYTES (SM_HS + 2 * KCH * 66 * 4)   // 156672

typedef unsigned long long ull;

__device__ float    g_h[2][Bsz * Hh];
__device__ unsigned g_cnt   = 0;
__device__ unsigned g_phase = 0;

__device__ __forceinline__ ull fma2(ull a, ull b, ull c) {
    ull d;
    asm("fma.rn.f32x2 %0, %1, %2, %3;" : "=l"(d) : "l"(a), "l"(b), "l"(c));
    return d;
}
__device__ __forceinline__ ull pack2(float a, float b) {
    ull d;
    asm("mov.b64 %0, {%1, %2};" : "=l"(d) : "f"(a), "f"(b));
    return d;
}
__device__ __forceinline__ ull dup2(float f) {
    ull d;
    asm("mov.b64 %0, {%1, %1};" : "=l"(d) : "f"(f));
    return d;
}
__device__ __forceinline__ float lo2(ull v) { return __uint_as_float((unsigned)v); }
__device__ __forceinline__ float hi2(ull v) { return __uint_as_float((unsigned)(v >> 32)); }
__device__ __forceinline__ float sigf(float x) { return 1.f / (1.f + __expf(-x)); }

__global__ void __launch_bounds__(NTHR, 1) gru_persist(
    const float* __restrict__ x,      // (B, T, I)
    const float* __restrict__ h0,     // (B, H)
    const float* __restrict__ w_ih,   // (3H, I)
    const float* __restrict__ w_hh,   // (3H, H)
    const float* __restrict__ b_ih,   // (3H)
    const float* __restrict__ b_hh,   // (3H)
    float* __restrict__ out)          // (B, T, H) then (B, H) tail
{
    extern __shared__ char sm[];
    ulonglong2* W01 = (ulonglong2*)(sm + SM_W01);   // [k*8 + tx]
    ull*        W2  = (ull*)(sm + SM_W2);           // [k*8 + tx]
    float*      HsB = (float*)(sm + SM_HS);         // [buf][kk][66]

    const int tid = threadIdx.x;
    const int bm  = blockIdx.x & 31;    // 32 m-tiles
    const int bb  = blockIdx.x >> 5;    // 4 batch-tiles
    const int m0  = bm * MT;
    const int b0  = bb * BT;
    const int tx  = tid & 7;            // m-pair lane
    const int TY  = tid >> 3;           // 0..31 -> 2 batches each
    const int m   = m0 + 2 * tx;

    // barrier base (stable: phase can't advance until every block arrives)
    unsigned bar_base = 0;
    if (tid == 0)
        asm volatile("ld.global.cg.u32 %0, [%1];" : "=r"(bar_base) : "l"(&g_phase));

    // ---- one-time: weight slice -> smem, transposed to [k][m-pair] ----
    for (int s = tid; s < KTOT * 8; s += NTHR) {
        const int kk = s >> 3, txx = s & 7, mm = m0 + 2 * txx;
        float wr0, wr1, wz0, wz1, wn0, wn1;
        if (kk < Hh) {
            wr0 = w_hh[(0 * Hh + mm) * Hh + kk]; wr1 = w_hh[(0 * Hh + mm + 1) * Hh + kk];
            wz0 = w_hh[(1 * Hh + mm) * Hh + kk]; wz1 = w_hh[(1 * Hh + mm + 1) * Hh + kk];
            wn0 = w_hh[(2 * Hh + mm) * Hh + kk]; wn1 = w_hh[(2 * Hh + mm + 1) * Hh + kk];
        } else {
            const int kx = kk - Hh;
            wr0 = w_ih[(0 * Hh + mm) * Ii + kx]; wr1 = w_ih[(0 * Hh + mm + 1) * Ii + kx];
            wz0 = w_ih[(1 * Hh + mm) * Ii + kx]; wz1 = w_ih[(1 * Hh + mm + 1) * Ii + kx];
            wn0 = w_ih[(2 * Hh + mm) * Ii + kx]; wn1 = w_ih[(2 * Hh + mm + 1) * Ii + kx];
        }
        W01[kk * 8 + txx] = make_ulonglong2(pack2(wr0, wr1), pack2(wz0, wz1));
        W2[kk * 8 + txx]  = pack2(wn0, wn1);
    }

    // biases, combined per m-pair
    const float2 cR  = make_float2(b_ih[m] + b_hh[m],           b_ih[m + 1] + b_hh[m + 1]);
    const float2 cZ  = make_float2(b_ih[Hh + m] + b_hh[Hh + m], b_ih[Hh + m + 1] + b_hh[Hh + m + 1]);
    const float2 cNx = make_float2(b_ih[2 * Hh + m],            b_ih[2 * Hh + m + 1]);
    const float2 cNh = make_float2(b_hh[2 * Hh + m],            b_hh[2 * Hh + m + 1]);

    __syncthreads();

    // staging mapping: thread -> (batch row bl, k offsets kq + j*16 + e)
    const int bl = tid >> 2;            // 0..63
    const int kq = (tid & 3) * 4;

    float4 st_regs[4];

    for (int t = 0; t < Tt; t++) {
        const float* hsrc = (t == 0) ? h0 : g_h[t & 1];
        float*       hdst = g_h[(t + 1) & 1];

        ull aR[2] = {0, 0}, aZ[2] = {0, 0}, aNh[2] = {0, 0}, aNx[2] = {0, 0};

        auto ldg_chunk = [&](int c) {
            const float* p = (c < 8)
                ? hsrc + (size_t)(b0 + bl) * Hh + c * KCH + kq
                : x + ((size_t)(b0 + bl) * Tt + t) * Ii + (c - 8) * KCH + kq;
            #pragma unroll
            for (int j = 0; j < 4; j++)
                st_regs[j] = __ldcg((const float4*)(p + j * 16));
        };
        auto sts_chunk = [&](int buf) {
            float* H = HsB + buf * (KCH * 66);
            #pragma unroll
            for (int j = 0; j < 4; j++) {
                const int kl = kq + j * 16;
                H[(kl + 0) * 66 + bl] = st_regs[j].x;
                H[(kl + 1) * 66 + bl] = st_regs[j].y;
                H[(kl + 2) * 66 + bl] = st_regs[j].z;
                H[(kl + 3) * 66 + bl] = st_regs[j].w;
            }
        };
        auto compute_h = [&](int buf, int kc) {
            const float* H = HsB + buf * (KCH * 66);
            #pragma unroll 16
            for (int kk = 0; kk < KCH; kk++) {
                ulonglong2 w01 = W01[(kc + kk) * 8 + tx];
                ull        w2v = W2[(kc + kk) * 8 + tx];
                float2 h2 = *(const float2*)(H + kk * 66 + 2 * TY);
                ull d0 = dup2(h2.x), d1 = dup2(h2.y);
                aR[0]  = fma2(d0, w01.x, aR[0]);  aR[1]  = fma2(d1, w01.x, aR[1]);
                aZ[0]  = fma2(d0, w01.y, aZ[0]);  aZ[1]  = fma2(d1, w01.y, aZ[1]);
                aNh[0] = fma2(d0, w2v,   aNh[0]); aNh[1] = fma2(d1, w2v,   aNh[1]);
            }
        };
        auto compute_x = [&](int buf, int kc) {
            const float* H = HsB + buf * (KCH * 66);
            #pragma unroll 16
            for (int kk = 0; kk < KCH; kk++) {
                ulonglong2 w01 = W01[(kc + kk) * 8 + tx];
                ull        w2v = W2[(kc + kk) * 8 + tx];
                float2 h2 = *(const float2*)(H + kk * 66 + 2 * TY);
                ull d0 = dup2(h2.x), d1 = dup2(h2.y);
                aR[0]  = fma2(d0, w01.x, aR[0]);  aR[1]  = fma2(d1, w01.x, aR[1]);
                aZ[0]  = fma2(d0, w01.y, aZ[0]);  aZ[1]  = fma2(d1, w01.y, aZ[1]);
                aNx[0] = fma2(d0, w2v,   aNx[0]); aNx[1] = fma2(d1, w2v,   aNx[1]);
            }
        };

        // double-buffered chunk pipeline
        ldg_chunk(0);
        sts_chunk(0);
        ldg_chunk(1);
        __syncthreads();
        #pragma unroll 1
        for (int c = 0; c < NCH; c++) {
            const int buf = c & 1;
            if (c + 1 < NCH) sts_chunk((c + 1) & 1);
            if (c + 2 < NCH) ldg_chunk(c + 2);
            if (c < 8) compute_h(buf, c * KCH);
            else       compute_x(buf, c * KCH);
            __syncthreads();
        }

        // ---- gates epilogue (fully local) ----
        #pragma unroll
        for (int i2 = 0; i2 < 2; i2++) {
            const int b = b0 + 2 * TY + i2;
            float2 hp = __ldcg((const float2*)(hsrc + (size_t)b * Hh + m));

            float rl = sigf(lo2(aR[i2]) + cR.x);
            float rh = sigf(hi2(aR[i2]) + cR.y);
            float zl = sigf(lo2(aZ[i2]) + cZ.x);
            float zh = sigf(hi2(aZ[i2]) + cZ.y);
            float nl = tanhf(lo2(aNx[i2]) + cNx.x + rl * (lo2(aNh[i2]) + cNh.x));
            float nh = tanhf(hi2(aNx[i2]) + cNx.y + rh * (hi2(aNh[i2]) + cNh.y));

            float hl = (1.f - zl) * nl + zl * hp.x;
            float hhv = (1.f - zh) * nh + zh * hp.y;
            hl  = fminf(fmaxf(hl,  -CLIPV), CLIPV);
            hhv = fminf(fmaxf(hhv, -CLIPV), CLIPV);

            float2 res = make_float2(hl, hhv);
            __stcg((float2*)(hdst + (size_t)b * Hh + m), res);
            *(float2*)(out + ((size_t)b * Tt + t) * Hh + m) = res;
            if (t == Tt - 1)
                *(float2*)(out + (size_t)Bsz * Tt * Hh + (size_t)b * Hh + m) = res;
        }

        // ---- grid barrier (monotonic phase, wrap-safe) ----
        __syncthreads();
        if (tid == 0) {
            __threadfence();
            unsigned old = atomicAdd(&g_cnt, 1u);
            if (old == (unsigned)(NBLK - 1)) {
                atomicExch(&g_cnt, 0u);
                __threadfence();
                atomicAdd(&g_phase, 1u);
            } else {
                const unsigned tgt = bar_base + (unsigned)(t + 1);
                unsigned v;
                do {
                    __nanosleep(32);
                    asm volatile("ld.global.cg.u32 %0, [%1];" : "=r"(v) : "l"(&g_phase));
                } while ((int)(v - tgt) < 0);
            }
            __threadfence();
        }
        __syncthreads();
    }
}

extern "C" void kernel_launch(void* const* d_in, const int* in_sizes, int n_in,
                              void* d_out, int out_size)
{
    (void)in_sizes; (void)n_in; (void)out_size;
    const float* x    = (const float*)d_in[0];
    const float* h0   = (const float*)d_in[1];
    const float* w_ih = (const float*)d_in[2];
    const float* w_hh = (const float*)d_in[3];
    const float* b_ih = (const float*)d_in[4];
    const float* b_hh = (const float*)d_in[5];
    float* out = (float*)d_out;

    cudaFuncSetAttribute(gru_persist, cudaFuncAttributeMaxDynamicSharedMemorySize,
                         SMEM_BYTES);

    gru_persist<<<NBLK, NTHR, SMEM_BYTES>>>(x, h0, w_ih, w_hh, b_ih, b_hh, out);
}